// round 12
// baseline (speedup 1.0000x reference)
#include <cuda_runtime.h>

#define NTOT 50000
#define AANCH 32
#define DDIM 64
#define NG 3125                      // NTOT/16
#define UB 8                         // u's per prep G-block
#define NBG ((NG + UB - 1) / UB)     // 391
#define MROWS 64                     // rows per main block
#define OSS 66                       // Os row stride (even -> 8B-aligned STS.64)

// plain C: g_C[a*64+k] = (1/32) * embeds[anchor[a]] . W1[k,:]
__device__ __align__(16) float g_C[AANCH * DDIM];
// pair-G: g_G2[u*64+k] = (E16[u]+E16[(u+1)%NG]).W2[k,:]/32 + b[k]
__device__ __align__(16) float g_G2[NG * DDIM];

typedef unsigned long long u64;
union F4U { float4 f; u64 u[2]; };

__device__ __forceinline__ u64 pack2(float x, float y) {
    u64 r; asm("mov.b64 %0, {%1,%2};" : "=l"(r) : "f"(x), "f"(y)); return r;
}
__device__ __forceinline__ u64 fma2(u64 a, u64 b, u64 c) {
    u64 d; asm("fma.rn.f32x2 %0, %1, %2, %3;" : "=l"(d) : "l"(a), "l"(b), "l"(c)); return d;
}
__device__ __forceinline__ u64 add2(u64 a, u64 b) {
    u64 d; asm("add.rn.f32x2 %0, %1, %2;" : "=l"(d) : "l"(a), "l"(b)); return d;
}
// non-sinkable global loads
__device__ __forceinline__ float ldg_force(const float* p) {
    float v; asm volatile("ld.global.nc.f32 %0, [%1];" : "=f"(v) : "l"(p)); return v;
}
__device__ __forceinline__ u64 ldg_force64(const float* p) {
    u64 v; asm volatile("ld.global.nc.b64 %0, [%1];" : "=l"(v) : "l"(p)); return v;
}

// ---------------------------------------------------------------------------
// prep: bid 0 -> anchor projections (g_C). bid 1..NBG: 8 G2 rows each
// (E16 computed in-block incl. the u0+8 neighbor, with wrap). 256 threads.
// ---------------------------------------------------------------------------
__global__ __launch_bounds__(256) void prep_kernel(
    const float* __restrict__ embeds,
    const int* __restrict__ anchor,
    const float* __restrict__ Wh,
    const float* __restrict__ bias)
{
    __shared__ float Wt[DDIM * 65];   // G path: W2t[d*65+k]. anchor path: W1[k*65+d]
    __shared__ float Buf[2080];       // G: Ps[18][64] + E32[8][64] | anchors: Es[32][65]
    const int t = threadIdx.x;

    if (blockIdx.x == 0) {
        // ---- anchor projections -> g_C
        #pragma unroll
        for (int i = 0; i < 16; i++) {
            int idx = t + i * 256;
            int k = idx >> 6, d = idx & 63;
            Wt[k * 65 + d] = Wh[k * 2 * DDIM + d];             // W1[k][d]
        }
        float* Es = Buf;                                       // [32][65]
        #pragma unroll
        for (int i = 0; i < 8; i++) {
            int idx = t + i * 256;
            int a = idx >> 6, d = idx & 63;
            Es[a * 65 + d] = embeds[(size_t)anchor[a] * DDIM + d];
        }
        __syncthreads();
        int ia = t >> 3;
        int kbase = (t & 7) * 8;
        float s[8];
        #pragma unroll
        for (int kk = 0; kk < 8; kk++) s[kk] = 0.f;
        #pragma unroll 8
        for (int d = 0; d < DDIM; d++) {
            float e = Es[ia * 65 + d];
            #pragma unroll
            for (int kk = 0; kk < 8; kk++) s[kk] += e * Wt[(kbase + kk) * 65 + d];
        }
        #pragma unroll
        for (int kk = 0; kk < 8; kk++)
            g_C[ia * DDIM + kbase + kk] = s[kk] * (1.0f / 32.0f);
        return;
    }

    // ---- G path
    const int u0 = (blockIdx.x - 1) * UB;
    #pragma unroll
    for (int i = 0; i < 4; i++) {
        int idx = t + i * 256;            // stage W2 transposed
        int k = idx >> 4, dq = idx & 15;
        float4 v = *(const float4*)(Wh + k * 2 * DDIM + DDIM + 4 * dq);
        Wt[(4 * dq + 0) * 65 + k] = v.x;
        Wt[(4 * dq + 1) * 65 + k] = v.y;
        Wt[(4 * dq + 2) * 65 + k] = v.z;
        Wt[(4 * dq + 3) * 65 + k] = v.w;
    }
    float* Ps = Buf;                      // [18][64] 8-row partial sums
    for (int s = t; s < (UB + 1) * 32; s += 256) {
        int uu = s >> 5, h = (s >> 4) & 1, c = s & 15;
        int rb = 16 * (u0 + uu);
        if (rb >= NTOT) rb -= NTOT;       // wrap
        const float4* src = (const float4*)(embeds + (size_t)(rb + 8 * h) * DDIM) + c;
        float4 a = make_float4(0.f, 0.f, 0.f, 0.f);
        #pragma unroll
        for (int j = 0; j < 8; j++) {
            float4 v = src[j * 16];
            a.x += v.x; a.y += v.y; a.z += v.z; a.w += v.w;
        }
        float* dst = Ps + (uu * 2 + h) * DDIM + 4 * c;
        dst[0] = a.x; dst[1] = a.y; dst[2] = a.z; dst[3] = a.w;
    }
    __syncthreads();
    float* E32 = Buf + 18 * DDIM;         // [8][64]
    #pragma unroll
    for (int i = 0; i < 2; i++) {
        int s = t + i * 256;
        int uu = s >> 6, d = s & 63;
        E32[uu * DDIM + d] =
            Ps[(2 * uu) * DDIM + d] + Ps[(2 * uu + 1) * DDIM + d] +
            Ps[(2 * uu + 2) * DDIM + d] + Ps[(2 * uu + 3) * DDIM + d];
    }
    __syncthreads();
    {
        int k = t & 63;
        int uu0 = t >> 6;
        float b = __ldg(bias + k);
        #pragma unroll
        for (int ii = 0; ii < 2; ii++) {
            int uu = uu0 + 4 * ii;
            int u = u0 + uu;
            float s = 0.f;
            #pragma unroll 16
            for (int d = 0; d < DDIM; d++)
                s += E32[uu * DDIM + d] * Wt[d * 65 + k];
            if (u < NG)
                g_G2[u * DDIM + k] = s * (1.0f / 32.0f) + b;
        }
    }
}

// ---------------------------------------------------------------------------
// main: block = 64 rows x 64 cols, 128 threads; warp = 64 rows x 16 cols.
// Epilogue: G2 fused into the transpose (forced LDG.64 prefetch, add.f32x2,
// 8B-aligned STS.64 into stride-66 rows), then LDS.64x2 + STG.128 copy-out.
// ---------------------------------------------------------------------------
__global__ __launch_bounds__(128) void main_kernel(
    const float* __restrict__ dists,
    float* __restrict__ out)
{
    __shared__ __align__(16) float Cs[AANCH * DDIM];   // 8 KB
    __shared__ __align__(16) float Os[MROWS * OSS];    // 16.5 KB
    const int t = threadIdx.x;
    const int lane = t & 31;
    const int wid = t >> 5;
    const int c0 = wid * 16;
    const int rowbase = blockIdx.x * MROWS;

    int n0 = rowbase + lane;      if (n0 >= NTOT) n0 = NTOT - 1;
    int n1 = rowbase + 32 + lane; if (n1 >= NTOT) n1 = NTOT - 1;

    // dists loads (prep-independent): issue before the PDL wait
    float dv0[32], dv1[32];
    #pragma unroll
    for (int a = 0; a < 32; a++) dv0[a] = ldg_force(dists + (size_t)a * NTOT + n0);
    #pragma unroll
    for (int a = 0; a < 32; a++) dv1[a] = ldg_force(dists + (size_t)a * NTOT + n1);

    asm volatile("griddepcontrol.wait;" ::: "memory");

    {   // stage C
        float4* dst = (float4*)Cs;
        const float4* src = (const float4*)g_C;
        #pragma unroll
        for (int i = 0; i < 4; i++)
            dst[t + i * 128] = src[t + i * 128];
    }
    __syncthreads();

    u64 acc0[8], acc1[8];
    #pragma unroll
    for (int q = 0; q < 8; q++) { acc0[q] = 0ULL; acc1[q] = 0ULL; }

    const float4* Crow = (const float4*)Cs + (c0 >> 2);
    #pragma unroll
    for (int a = 0; a < 32; a++) {
        u64 b0 = pack2(dv0[a], dv0[a]);
        u64 b1 = pack2(dv1[a], dv1[a]);
        #pragma unroll
        for (int qq = 0; qq < 4; qq++) {
            F4U cu; cu.f = Crow[a * 16 + qq];              // broadcast LDS.128
            acc0[2 * qq]     = fma2(b0, cu.u[0], acc0[2 * qq]);
            acc0[2 * qq + 1] = fma2(b0, cu.u[1], acc0[2 * qq + 1]);
            acc1[2 * qq]     = fma2(b1, cu.u[0], acc1[2 * qq]);
            acc1[2 * qq + 1] = fma2(b1, cu.u[1], acc1[2 * qq + 1]);
        }
    }

    // G2 pair prefetch (8B-aligned: DDIM even, c0 even, 2qq even)
    const int ua = (2 * (rowbase + lane)) % NG;
    const int ub = (2 * (rowbase + 32 + lane)) % NG;
    u64 g0[8], g1[8];
    #pragma unroll
    for (int qq = 0; qq < 8; qq++) {
        g0[qq] = ldg_force64(g_G2 + (size_t)ua * DDIM + c0 + 2 * qq);
        g1[qq] = ldg_force64(g_G2 + (size_t)ub * DDIM + c0 + 2 * qq);
    }

    // transpose with fused G add: STS.64 into stride-66 rows (8B-aligned)
    #pragma unroll
    for (int qq = 0; qq < 8; qq++) {
        *(u64*)(Os + lane * OSS + c0 + 2 * qq)        = add2(acc0[qq], g0[qq]);
        *(u64*)(Os + (32 + lane) * OSS + c0 + 2 * qq) = add2(acc1[qq], g1[qq]);
    }
    __syncthreads();

    // copy-out: 2 x LDS.64 + 1 x STG.128 per 16B chunk (out is 16B-aligned)
    const int rows_valid = NTOT - rowbase;
    #pragma unroll
    for (int i = 0; i < 8; i++) {
        int idx = t + i * 128;
        int r = idx >> 4, c = idx & 15;
        if (r < rows_valid) {
            u64 lo = *(const u64*)(Os + r * OSS + 4 * c);
            u64 hi = *(const u64*)(Os + r * OSS + 4 * c + 2);
            F4U v; v.u[0] = lo; v.u[1] = hi;
            *(float4*)(out + (size_t)(rowbase + r) * DDIM + 4 * c) = v.f;
        }
    }
}

// ---------------------------------------------------------------------------
extern "C" void kernel_launch(void* const* d_in, const int* in_sizes, int n_in,
                              void* d_out, int out_size)
{
    const float* embeds = (const float*)d_in[0];   // (N, D)
    const float* dists  = (const float*)d_in[1];   // (A, N)
    const int*   anchor = (const int*)d_in[2];     // (A,)
    const float* Wh     = (const float*)d_in[3];   // (D, 2D)
    const float* bias   = (const float*)d_in[4];   // (D,)
    float* out = (float*)d_out;
    (void)in_sizes; (void)n_in; (void)out_size;

    prep_kernel<<<NBG + 1, 256>>>(embeds, anchor, Wh, bias);

    // PDL: main launches early; its dists loads overlap prep's tail.
    cudaLaunchConfig_t cfg = {};
    cfg.gridDim  = dim3((NTOT + MROWS - 1) / MROWS);   // 782
    cfg.blockDim = dim3(128);
    cudaLaunchAttribute attr[1];
    attr[0].id = cudaLaunchAttributeProgrammaticStreamSerialization;
    attr[0].val.programmaticStreamSerializationAllowed = 1;
    cfg.attrs = attr;
    cfg.numAttrs = 1;
    cudaLaunchKernelEx(&cfg, main_kernel, dists, out);
}

// round 13
// speedup vs baseline: 1.1919x; 1.1919x over previous
#include <cuda_runtime.h>

#define NTOT 50000
#define AANCH 32
#define DDIM 64
#define NG 3125                      // NTOT/16
#define UB 8                         // u's per prep G-block
#define NBG ((NG + UB - 1) / UB)     // 391
#define MROWS 64                     // rows per main block

// plain C: g_C[a*64+k] = (1/32) * embeds[anchor[a]] . W1[k,:]
__device__ __align__(16) float g_C[AANCH * DDIM];
// pair-G: g_G2[u*64+k] = (E16[u]+E16[(u+1)%NG]).W2[k,:]/32 + b[k]
__device__ __align__(16) float g_G2[NG * DDIM];

typedef unsigned long long u64;
union F4U { float4 f; u64 u[2]; };

__device__ __forceinline__ u64 pack2(float x, float y) {
    u64 r; asm("mov.b64 %0, {%1,%2};" : "=l"(r) : "f"(x), "f"(y)); return r;
}
__device__ __forceinline__ void unpack2(u64 v, float& x, float& y) {
    asm("mov.b64 {%0,%1}, %2;" : "=f"(x), "=f"(y) : "l"(v));
}
__device__ __forceinline__ u64 fma2(u64 a, u64 b, u64 c) {
    u64 d; asm("fma.rn.f32x2 %0, %1, %2, %3;" : "=l"(d) : "l"(a), "l"(b), "l"(c)); return d;
}
// non-sinkable global loads
__device__ __forceinline__ float ldg_force(const float* p) {
    float v; asm volatile("ld.global.nc.f32 %0, [%1];" : "=f"(v) : "l"(p)); return v;
}
__device__ __forceinline__ float4 ldg_force128(const float* p) {
    float4 v;
    asm volatile("ld.global.nc.v4.f32 {%0,%1,%2,%3}, [%4];"
                 : "=f"(v.x), "=f"(v.y), "=f"(v.z), "=f"(v.w) : "l"(p));
    return v;
}

// ---------------------------------------------------------------------------
// prep: bid 0 -> anchor projections (g_C). bid 1..NBG: 8 G2 rows each
// (E16 computed in-block incl. the u0+8 neighbor, with wrap). 256 threads.
// ---------------------------------------------------------------------------
__global__ __launch_bounds__(256) void prep_kernel(
    const float* __restrict__ embeds,
    const int* __restrict__ anchor,
    const float* __restrict__ Wh,
    const float* __restrict__ bias)
{
    __shared__ float Wt[DDIM * 65];   // G path: W2t[d*65+k]. anchor path: W1[k*65+d]
    __shared__ float Buf[2080];       // G: Ps[18][64] + E32[8][64] | anchors: Es[32][65]
    const int t = threadIdx.x;

    if (blockIdx.x == 0) {
        // ---- anchor projections -> g_C
        #pragma unroll
        for (int i = 0; i < 16; i++) {
            int idx = t + i * 256;
            int k = idx >> 6, d = idx & 63;
            Wt[k * 65 + d] = Wh[k * 2 * DDIM + d];             // W1[k][d]
        }
        float* Es = Buf;                                       // [32][65]
        #pragma unroll
        for (int i = 0; i < 8; i++) {
            int idx = t + i * 256;
            int a = idx >> 6, d = idx & 63;
            Es[a * 65 + d] = embeds[(size_t)anchor[a] * DDIM + d];
        }
        __syncthreads();
        int ia = t >> 3;
        int kbase = (t & 7) * 8;
        float s[8];
        #pragma unroll
        for (int kk = 0; kk < 8; kk++) s[kk] = 0.f;
        #pragma unroll 8
        for (int d = 0; d < DDIM; d++) {
            float e = Es[ia * 65 + d];
            #pragma unroll
            for (int kk = 0; kk < 8; kk++) s[kk] += e * Wt[(kbase + kk) * 65 + d];
        }
        #pragma unroll
        for (int kk = 0; kk < 8; kk++)
            g_C[ia * DDIM + kbase + kk] = s[kk] * (1.0f / 32.0f);
        return;
    }

    // ---- G path
    const int u0 = (blockIdx.x - 1) * UB;
    #pragma unroll
    for (int i = 0; i < 4; i++) {
        int idx = t + i * 256;            // stage W2 transposed
        int k = idx >> 4, dq = idx & 15;
        float4 v = *(const float4*)(Wh + k * 2 * DDIM + DDIM + 4 * dq);
        Wt[(4 * dq + 0) * 65 + k] = v.x;
        Wt[(4 * dq + 1) * 65 + k] = v.y;
        Wt[(4 * dq + 2) * 65 + k] = v.z;
        Wt[(4 * dq + 3) * 65 + k] = v.w;
    }
    float* Ps = Buf;                      // [18][64] 8-row partial sums
    for (int s = t; s < (UB + 1) * 32; s += 256) {
        int uu = s >> 5, h = (s >> 4) & 1, c = s & 15;
        int rb = 16 * (u0 + uu);
        if (rb >= NTOT) rb -= NTOT;       // wrap
        const float4* src = (const float4*)(embeds + (size_t)(rb + 8 * h) * DDIM) + c;
        float4 a = make_float4(0.f, 0.f, 0.f, 0.f);
        #pragma unroll
        for (int j = 0; j < 8; j++) {
            float4 v = src[j * 16];
            a.x += v.x; a.y += v.y; a.z += v.z; a.w += v.w;
        }
        float* dst = Ps + (uu * 2 + h) * DDIM + 4 * c;
        dst[0] = a.x; dst[1] = a.y; dst[2] = a.z; dst[3] = a.w;
    }
    __syncthreads();
    float* E32 = Buf + 18 * DDIM;         // [8][64]
    #pragma unroll
    for (int i = 0; i < 2; i++) {
        int s = t + i * 256;
        int uu = s >> 6, d = s & 63;
        E32[uu * DDIM + d] =
            Ps[(2 * uu) * DDIM + d] + Ps[(2 * uu + 1) * DDIM + d] +
            Ps[(2 * uu + 2) * DDIM + d] + Ps[(2 * uu + 3) * DDIM + d];
    }
    __syncthreads();
    {
        int k = t & 63;
        int uu0 = t >> 6;
        float b = __ldg(bias + k);
        #pragma unroll
        for (int ii = 0; ii < 2; ii++) {
            int uu = uu0 + 4 * ii;
            int u = u0 + uu;
            float s = 0.f;
            #pragma unroll 16
            for (int d = 0; d < DDIM; d++)
                s += E32[uu * DDIM + d] * Wt[d * 65 + k];
            if (u < NG)
                g_G2[u * DDIM + k] = s * (1.0f / 32.0f) + b;
        }
    }
}

// ---------------------------------------------------------------------------
// main: block = 64 rows x 64 cols, 128 threads; warp = 64 rows x 16 cols.
// Epilogue: block's 64 G2 rows staged COALESCED into shared (LDG.128 held in
// regs across the alias barrier), then all-smem add + coalesced STG.
// ---------------------------------------------------------------------------
__global__ __launch_bounds__(128) void main_kernel(
    const float* __restrict__ dists,
    float* __restrict__ out)
{
    // Os [64][65] = 4160 fl; Gs [64][64] = 4096 fl (aliases dead Cs region)
    __shared__ __align__(16) float smem[MROWS * 65 + MROWS * DDIM];   // 33 KB
    float* Os = smem;
    float* Gs = smem + MROWS * 65;
    float* Cs = smem + MROWS * 65;        // mainloop-phase alias of Gs region
    const int t = threadIdx.x;
    const int lane = t & 31;
    const int wid = t >> 5;
    const int c0 = wid * 16;
    const int rowbase = blockIdx.x * MROWS;

    int n0 = rowbase + lane;      if (n0 >= NTOT) n0 = NTOT - 1;
    int n1 = rowbase + 32 + lane; if (n1 >= NTOT) n1 = NTOT - 1;

    // dists loads (prep-independent): issue before the PDL wait
    float dv0[32], dv1[32];
    #pragma unroll
    for (int a = 0; a < 32; a++) dv0[a] = ldg_force(dists + (size_t)a * NTOT + n0);
    #pragma unroll
    for (int a = 0; a < 32; a++) dv1[a] = ldg_force(dists + (size_t)a * NTOT + n1);

    asm volatile("griddepcontrol.wait;" ::: "memory");

    {   // stage C into Cs (8 KB, L2-resident)
        float4* dst = (float4*)Cs;
        const float4* src = (const float4*)g_C;
        #pragma unroll
        for (int i = 0; i < 4; i++)
            dst[t + i * 128] = src[t + i * 128];
    }
    __syncthreads();

    u64 acc0[8], acc1[8];
    #pragma unroll
    for (int q = 0; q < 8; q++) { acc0[q] = 0ULL; acc1[q] = 0ULL; }

    const float4* Crow = (const float4*)Cs + (c0 >> 2);
    #pragma unroll
    for (int a = 0; a < 32; a++) {
        u64 b0 = pack2(dv0[a], dv0[a]);
        u64 b1 = pack2(dv1[a], dv1[a]);
        #pragma unroll
        for (int qq = 0; qq < 4; qq++) {
            F4U cu; cu.f = Crow[a * 16 + qq];              // broadcast LDS.128
            acc0[2 * qq]     = fma2(b0, cu.u[0], acc0[2 * qq]);
            acc0[2 * qq + 1] = fma2(b0, cu.u[1], acc0[2 * qq + 1]);
            acc1[2 * qq]     = fma2(b1, cu.u[0], acc1[2 * qq]);
            acc1[2 * qq + 1] = fma2(b1, cu.u[1], acc1[2 * qq + 1]);
        }
    }

    // issue coalesced G2 loads NOW (held in regs; Cs still live, so STS later)
    // task (gr, c): lanes 0-15 read one 256B G2 row segment -> coalesced
    float4 gv[8];
    int grs[8];
    #pragma unroll
    for (int i = 0; i < 8; i++) {
        int idx = t + i * 128;
        int gr = idx >> 4, c = idx & 15;
        grs[i] = idx;
        int u = (2 * (rowbase + gr)) % NG;
        gv[i] = ldg_force128(g_G2 + (size_t)u * DDIM + 4 * c);
    }

    __syncthreads();   // everyone done reading Cs; safe to overwrite with Gs

    // store Gs (STS.128, 16B-aligned) + transpose into Os (scalar, stride 65)
    #pragma unroll
    for (int i = 0; i < 8; i++) {
        int gr = grs[i] >> 4, c = grs[i] & 15;
        *(float4*)(Gs + gr * DDIM + 4 * c) = gv[i];
    }
    #pragma unroll
    for (int qq = 0; qq < 8; qq++) {
        float x, y;
        unpack2(acc0[qq], x, y);
        Os[lane * 65 + c0 + 2 * qq]     = x;
        Os[lane * 65 + c0 + 2 * qq + 1] = y;
        unpack2(acc1[qq], x, y);
        Os[(32 + lane) * 65 + c0 + 2 * qq]     = x;
        Os[(32 + lane) * 65 + c0 + 2 * qq + 1] = y;
    }
    __syncthreads();

    // all-smem epilogue: no global loads, no wrap ALU
    const int rows_valid = NTOT - rowbase;
    const int k = t & 63;
    int r = t >> 6;
    #pragma unroll 8
    for (int i = 0; i < MROWS / 2; i++, r += 2) {
        if (r < rows_valid)
            out[(size_t)(rowbase + r) * DDIM + k] = Os[r * 65 + k] + Gs[r * DDIM + k];
    }
}

// ---------------------------------------------------------------------------
extern "C" void kernel_launch(void* const* d_in, const int* in_sizes, int n_in,
                              void* d_out, int out_size)
{
    const float* embeds = (const float*)d_in[0];   // (N, D)
    const float* dists  = (const float*)d_in[1];   // (A, N)
    const int*   anchor = (const int*)d_in[2];     // (A,)
    const float* Wh     = (const float*)d_in[3];   // (D, 2D)
    const float* bias   = (const float*)d_in[4];   // (D,)
    float* out = (float*)d_out;
    (void)in_sizes; (void)n_in; (void)out_size;

    prep_kernel<<<NBG + 1, 256>>>(embeds, anchor, Wh, bias);

    // PDL: main launches early; its dists loads overlap prep's tail.
    cudaLaunchConfig_t cfg = {};
    cfg.gridDim  = dim3((NTOT + MROWS - 1) / MROWS);   // 782
    cfg.blockDim = dim3(128);
    cudaLaunchAttribute attr[1];
    attr[0].id = cudaLaunchAttributeProgrammaticStreamSerialization;
    attr[0].val.programmaticStreamSerializationAllowed = 1;
    cfg.attrs = attr;
    cfg.numAttrs = 1;
    cudaLaunchKernelEx(&cfg, main_kernel, dists, out);
}